// round 6
// baseline (speedup 1.0000x reference)
#include <cuda_runtime.h>
#include <cuda_bf16.h>
#include <cstdint>

// Grouped conv2d via implicit GEMM on mma.sync (HMMA), split-bf16 3-pass.
// x[16,256,128,128] * W[512,16,3,3] (groups=16) + b -> out[16,512,128,128]
// R6: 3 CTAs/SM (reg+smem diet): interleaved hi/lo x plane (+prmt extract),
//     XOR-swizzled B frags, warp tile split into 2 halves of 2 segs.

#define THREADS 256

// ---- smem layout (bytes) ----
// B frags: 18 combos x 1024B (32 lanes x 32B), 16B-block XOR swizzle
#define SWF_OFF   0
#define SWF_BYTES (18 * 1024)               // 18432
// x plane: [row 0..5][col 0..129][ci 0..15] u32 (hi<<16|lo), ci rotated by (col&3)*4
#define XCOL_STRIDE 64
#define XROW_STRIDE (130 * XCOL_STRIDE)     // 8320
#define SX_OFF    SWF_BYTES                 // 18432
#define SX_BYTES  (6 * XROW_STRIDE)         // 49920
#define SBIAS_OFF (SX_OFF + SX_BYTES)       // 68352
#define SMEM_TOTAL (SBIAS_OFF + 128)        // 68480

__device__ __forceinline__ void mma16816(float& c0, float& c1, float& c2, float& c3,
                                         uint32_t a0, uint32_t a1, uint32_t a2, uint32_t a3,
                                         uint32_t b0, uint32_t b1) {
    asm volatile("mma.sync.aligned.m16n8k16.row.col.f32.bf16.bf16.f32 "
                 "{%0,%1,%2,%3}, {%4,%5,%6,%7}, {%8,%9}, {%0,%1,%2,%3};"
                 : "+f"(c0), "+f"(c1), "+f"(c2), "+f"(c3)
                 : "r"(a0), "r"(a1), "r"(a2), "r"(a3), "r"(b0), "r"(b1));
}

__device__ __forceinline__ uint32_t prmt(uint32_t a, uint32_t b, uint32_t sel) {
    uint32_t d;
    asm("prmt.b32 %0, %1, %2, %3;" : "=r"(d) : "r"(a), "r"(b), "r"(sel));
    return d;
}

// pack one float into u32 = (bf16_hi << 16) | bf16_lo_residual
__device__ __forceinline__ uint32_t split_pack(float v) {
    __nv_bfloat16 hb = __float2bfloat16(v);
    __nv_bfloat16 lb = __float2bfloat16(v - __bfloat162float(hb));
    return ((uint32_t)__bfloat16_as_ushort(hb) << 16) | (uint32_t)__bfloat16_as_ushort(lb);
}

__device__ __forceinline__ uint32_t bf16_hi_lo_pack(float v0, float v1, int want_lo) {
    __nv_bfloat16 h0 = __float2bfloat16(v0);
    __nv_bfloat16 h1 = __float2bfloat16(v1);
    __nv_bfloat16 e0, e1;
    if (want_lo) {
        e0 = __float2bfloat16(v0 - __bfloat162float(h0));
        e1 = __float2bfloat16(v1 - __bfloat162float(h1));
    } else {
        e0 = h0; e1 = h1;
    }
    return (uint32_t)__bfloat16_as_ushort(e0) | ((uint32_t)__bfloat16_as_ushort(e1) << 16);
}

__device__ __forceinline__ uint32_t bswz(uint32_t logical) {
    return logical ^ (((logical >> 7) & 1u) << 4);
}

__global__ __launch_bounds__(THREADS, 3)
void grouped_conv_hmma(const float* __restrict__ x,
                       const float* __restrict__ w,
                       const float* __restrict__ bias,
                       float* __restrict__ out)
{
    extern __shared__ char smem[];
    uint32_t* swf = (uint32_t*)(smem + SWF_OFF);
    char* sx = smem + SX_OFF;
    float* sbias = (float*)(smem + SBIAS_OFF);

    const int tid = threadIdx.x;
    const int wid = tid >> 5;
    const int lane = tid & 31;

    const int hb = blockIdx.x;          // 0..31  (4-row blocks)
    const int ng = blockIdx.y;          // 0..255
    const int n  = ng >> 4;
    const int g  = ng & 15;
    const int h0 = hb * 4;

    // ---- stage x: rows h0-1..h0+4, cols -1..128, u32 = hi<<16|lo, ci pairs ----
    const float* xg = x + (size_t)(n * 256 + g * 16) * 16384;
    for (int idx = tid; idx < 6 * 8 * 130; idx += THREADS) {
        int c   = idx % 130;
        int t   = idx / 130;
        int ci2 = t % 8;                // ci pair index (ci = 2*ci2)
        int r   = t / 8;                // 0..5
        int gh = h0 - 1 + r;
        int gw = c - 1;
        float v0 = 0.0f, v1 = 0.0f;
        if ((unsigned)gh < 128u && (unsigned)gw < 128u) {
            const float* p = xg + (ci2 * 2) * 16384 + gh * 128 + gw;
            v0 = p[0];
            v1 = p[16384];
        }
        int rci = (2 * ci2 + (c & 3) * 4) & 15;   // rotation keeps pair adjacent
        uint32_t off = (uint32_t)(r * XROW_STRIDE + c * XCOL_STRIDE + rci * 4);
        uint2 u; u.x = split_pack(v0); u.y = split_pack(v1);
        *(uint2*)(sx + off) = u;
    }

    // ---- stage W as B fragments, XOR-swizzled 32B/lane ----
    const float* wgp = w + (size_t)(g * 32) * 144;
    for (int idx = tid; idx < 18 * 32 * 8; idx += THREADS) {
        int slot  = idx & 7;
        int lane2 = (idx >> 3) & 31;
        int combo = idx >> 8;           // 0..17 = tap*2 + hl
        int tap = combo >> 1, hl = combo & 1;
        int g4 = lane2 >> 2, t4 = lane2 & 3;
        int nt = slot >> 1, rr = slot & 1;
        int co  = nt * 8 + g4;
        int ci0 = 2 * t4 + 8 * rr;
        float v0 = wgp[co * 144 + ci0 * 9 + tap];
        float v1 = wgp[co * 144 + (ci0 + 1) * 9 + tap];
        uint32_t logical = (uint32_t)(combo * 1024 + lane2 * 32 + slot * 4);
        *(uint32_t*)((char*)swf + bswz(logical)) = bf16_hi_lo_pack(v0, v1, hl);
    }
    if (tid < 32) sbias[tid] = bias[g * 32 + tid];
    __syncthreads();

    // ---- main: warp = (row, w-half); 2 halves of 2 segs each ----
    const int wrow  = wid >> 1;          // 0..3
    const int whalf = (wid & 1) * 64;
    const int g4 = lane >> 2, t4 = lane & 3;
    const int h = h0 + wrow;
    float* og = out + (size_t)(n * 512 + g * 32) * 16384 + (size_t)h * 128;

    float bias_lo[4], bias_hi[4];
    #pragma unroll
    for (int nt = 0; nt < 4; ++nt) {
        bias_lo[nt] = sbias[nt * 8 + 2 * t4];
        bias_hi[nt] = sbias[nt * 8 + 2 * t4 + 1];
    }

    #pragma unroll
    for (int half = 0; half < 2; ++half) {
        float acc[2][4][4];              // [seg2][nt][4]
        #pragma unroll
        for (int s = 0; s < 2; ++s)
            #pragma unroll
            for (int nt = 0; nt < 4; ++nt)
                #pragma unroll
                for (int i = 0; i < 4; ++i) acc[s][nt][i] = 0.0f;

        #pragma unroll
        for (int tap = 0; tap < 9; ++tap) {
            const int dh = tap / 3, dw = tap % 3;
            // B fragments (hi @ combo 2*tap, lo @ +1024B), swizzled
            const uint32_t bl0g = (uint32_t)(tap * 2048 + lane * 32);
            const uint32_t bph = bswz(bl0g);
            uint4 bh0 = *(const uint4*)((char*)swf + bph);
            uint4 bh1 = *(const uint4*)((char*)swf + (bph ^ 16));
            uint4 bl0 = *(const uint4*)((char*)swf + bph + 1024);
            uint4 bl1 = *(const uint4*)((char*)swf + (bph ^ 16) + 1024);

            #pragma unroll
            for (int s = 0; s < 2; ++s) {
                const int w0 = whalf + (half * 2 + s) * 16;
                const int col = w0 + dw + g4;           // smem col of px0
                const int rot = (col & 3) * 4;
                const uint32_t colb = (uint32_t)((wrow + dh) * XROW_STRIDE + col * XCOL_STRIDE);
                const uint32_t a_lo = colb + (uint32_t)(((2 * t4 + rot) & 15) * 4);
                const uint32_t a_hi = colb + (uint32_t)(((2 * t4 + 8 + rot) & 15) * 4);

                uint2 p0 = *(const uint2*)(sx + a_lo);          // px0, ci 2t4..
                uint2 p1 = *(const uint2*)(sx + a_lo + 8 * XCOL_STRIDE); // px0+8
                uint2 q0 = *(const uint2*)(sx + a_hi);
                uint2 q1 = *(const uint2*)(sx + a_hi + 8 * XCOL_STRIDE);

                uint32_t ah0 = prmt(p0.x, p0.y, 0x7632), al0 = prmt(p0.x, p0.y, 0x5410);
                uint32_t ah1 = prmt(p1.x, p1.y, 0x7632), al1 = prmt(p1.x, p1.y, 0x5410);
                uint32_t ah2 = prmt(q0.x, q0.y, 0x7632), al2 = prmt(q0.x, q0.y, 0x5410);
                uint32_t ah3 = prmt(q1.x, q1.y, 0x7632), al3 = prmt(q1.x, q1.y, 0x5410);

                float* a0 = acc[s][0];
                float* a1 = acc[s][1];
                float* a2 = acc[s][2];
                float* a3 = acc[s][3];

                mma16816(a0[0], a0[1], a0[2], a0[3], ah0, ah1, ah2, ah3, bh0.x, bh0.y);
                mma16816(a1[0], a1[1], a1[2], a1[3], ah0, ah1, ah2, ah3, bh0.z, bh0.w);
                mma16816(a2[0], a2[1], a2[2], a2[3], ah0, ah1, ah2, ah3, bh1.x, bh1.y);
                mma16816(a3[0], a3[1], a3[2], a3[3], ah0, ah1, ah2, ah3, bh1.z, bh1.w);

                mma16816(a0[0], a0[1], a0[2], a0[3], ah0, ah1, ah2, ah3, bl0.x, bl0.y);
                mma16816(a1[0], a1[1], a1[2], a1[3], ah0, ah1, ah2, ah3, bl0.z, bl0.w);
                mma16816(a2[0], a2[1], a2[2], a2[3], ah0, ah1, ah2, ah3, bl1.x, bl1.y);
                mma16816(a3[0], a3[1], a3[2], a3[3], ah0, ah1, ah2, ah3, bl1.z, bl1.w);

                mma16816(a0[0], a0[1], a0[2], a0[3], al0, al1, al2, al3, bh0.x, bh0.y);
                mma16816(a1[0], a1[1], a1[2], a1[3], al0, al1, al2, al3, bh0.z, bh0.w);
                mma16816(a2[0], a2[1], a2[2], a2[3], al0, al1, al2, al3, bh1.x, bh1.y);
                mma16816(a3[0], a3[1], a3[2], a3[3], al0, al1, al2, al3, bh1.z, bh1.w);
            }
        }

        // ---- epilogue for this half ----
        #pragma unroll
        for (int s = 0; s < 2; ++s) {
            const int w0 = whalf + (half * 2 + s) * 16;
            #pragma unroll
            for (int nt = 0; nt < 4; ++nt) {
                const size_t co0 = (size_t)(nt * 8 + 2 * t4) * 16384;
                og[co0 + w0 + g4]             = acc[s][nt][0] + bias_lo[nt];
                og[co0 + 16384 + w0 + g4]     = acc[s][nt][1] + bias_hi[nt];
                og[co0 + w0 + g4 + 8]         = acc[s][nt][2] + bias_lo[nt];
                og[co0 + 16384 + w0 + g4 + 8] = acc[s][nt][3] + bias_hi[nt];
            }
        }
    }
}

extern "C" void kernel_launch(void* const* d_in, const int* in_sizes, int n_in,
                              void* d_out, int out_size)
{
    const float* x = (const float*)d_in[0];
    const float* w = (const float*)d_in[1];
    const float* b = (const float*)d_in[2];
    float* out = (float*)d_out;

    cudaFuncSetAttribute(grouped_conv_hmma,
                         cudaFuncAttributeMaxDynamicSharedMemorySize, SMEM_TOTAL);

    dim3 grid(32, 256);   // 4-row h blocks, n*16+g
    grouped_conv_hmma<<<grid, THREADS, SMEM_TOTAL>>>(x, w, b, out);
}

// round 7
// speedup vs baseline: 2.0216x; 2.0216x over previous
#include <cuda_runtime.h>
#include <cuda_bf16.h>
#include <cstdint>

// Grouped conv2d via implicit GEMM on mma.sync (HMMA), split-bf16 3-pass.
// x[16,256,128,128] * W[512,16,3,3] (groups=16) + b -> out[16,512,128,128]
// R7: 3 CTAs/SM without spills: hi/lo x planes (no prmt), swizzled B frags,
//     warp tile in 2 halves of 2 segs (acc=32 regs), taps unroll 3.

#define THREADS 256

// ---- smem layout (bytes) ----
// B frags: 18 combos x 1024B (32 lanes x 32B), 16B-block XOR swizzle
#define SWF_OFF   0
#define SWF_BYTES (18 * 1024)               // 18432
// x planes hi/lo: [row 0..5][col 0..129][ci 0..15 bf16], col stride 36B
#define XCOL_STRIDE 36
#define XROW_STRIDE (130 * XCOL_STRIDE)     // 4680
#define XPLANE_BYTES (6 * XROW_STRIDE)      // 28080
#define SXH_OFF   SWF_BYTES                 // 18432
#define SXL_OFF   (SXH_OFF + XPLANE_BYTES)  // 46512
#define SBIAS_OFF (SXL_OFF + XPLANE_BYTES)  // 74592
#define SMEM_TOTAL (SBIAS_OFF + 128)        // 74720  (x3 = 224160 <= 228KB)

__device__ __forceinline__ void mma16816(float& c0, float& c1, float& c2, float& c3,
                                         uint32_t a0, uint32_t a1, uint32_t a2, uint32_t a3,
                                         uint32_t b0, uint32_t b1) {
    asm volatile("mma.sync.aligned.m16n8k16.row.col.f32.bf16.bf16.f32 "
                 "{%0,%1,%2,%3}, {%4,%5,%6,%7}, {%8,%9}, {%0,%1,%2,%3};"
                 : "+f"(c0), "+f"(c1), "+f"(c2), "+f"(c3)
                 : "r"(a0), "r"(a1), "r"(a2), "r"(a3), "r"(b0), "r"(b1));
}

__device__ __forceinline__ uint32_t bf16_hi_lo_pack(float v0, float v1, int want_lo) {
    __nv_bfloat16 h0 = __float2bfloat16(v0);
    __nv_bfloat16 h1 = __float2bfloat16(v1);
    __nv_bfloat16 e0, e1;
    if (want_lo) {
        e0 = __float2bfloat16(v0 - __bfloat162float(h0));
        e1 = __float2bfloat16(v1 - __bfloat162float(h1));
    } else {
        e0 = h0; e1 = h1;
    }
    return (uint32_t)__bfloat16_as_ushort(e0) | ((uint32_t)__bfloat16_as_ushort(e1) << 16);
}

__device__ __forceinline__ uint32_t bswz(uint32_t logical) {
    return logical ^ (((logical >> 7) & 1u) << 4);
}

__global__ __launch_bounds__(THREADS, 3)
void grouped_conv_hmma(const float* __restrict__ x,
                       const float* __restrict__ w,
                       const float* __restrict__ bias,
                       float* __restrict__ out)
{
    extern __shared__ char smem[];
    uint32_t* swf = (uint32_t*)(smem + SWF_OFF);
    char* sxh = smem + SXH_OFF;
    char* sxl = smem + SXL_OFF;
    float* sbias = (float*)(smem + SBIAS_OFF);

    const int tid = threadIdx.x;
    const int wid = tid >> 5;
    const int lane = tid & 31;

    const int hb = blockIdx.x;          // 0..31  (4-row blocks)
    const int ng = blockIdx.y;          // 0..255
    const int n  = ng >> 4;
    const int g  = ng & 15;
    const int h0 = hb * 4;

    // ---- stage x: rows h0-1..h0+4, cols -1..128, split bf16 hi/lo (ci pairs) ----
    const float* xg = x + (size_t)(n * 256 + g * 16) * 16384;
    for (int idx = tid; idx < 6 * 8 * 130; idx += THREADS) {
        int c   = idx % 130;
        int t   = idx / 130;
        int ci2 = t % 8;                // ci pair
        int r   = t / 8;                // 0..5
        int gh = h0 - 1 + r;
        int gw = c - 1;
        float v0 = 0.0f, v1 = 0.0f;
        if ((unsigned)gh < 128u && (unsigned)gw < 128u) {
            const float* p = xg + (ci2 * 2) * 16384 + gh * 128 + gw;
            v0 = p[0];
            v1 = p[16384];
        }
        uint32_t off = (uint32_t)(r * XROW_STRIDE + c * XCOL_STRIDE + ci2 * 4);
        *(uint32_t*)(sxh + off) = bf16_hi_lo_pack(v0, v1, 0);
        *(uint32_t*)(sxl + off) = bf16_hi_lo_pack(v0, v1, 1);
    }

    // ---- stage W as B fragments, XOR-swizzled 32B/lane ----
    const float* wgp = w + (size_t)(g * 32) * 144;
    for (int idx = tid; idx < 18 * 32 * 8; idx += THREADS) {
        int slot  = idx & 7;
        int lane2 = (idx >> 3) & 31;
        int combo = idx >> 8;           // 0..17 = tap*2 + hl
        int tap = combo >> 1, hl = combo & 1;
        int g4 = lane2 >> 2, t4 = lane2 & 3;
        int nt = slot >> 1, rr = slot & 1;
        int co  = nt * 8 + g4;
        int ci0 = 2 * t4 + 8 * rr;
        float v0 = wgp[co * 144 + ci0 * 9 + tap];
        float v1 = wgp[co * 144 + (ci0 + 1) * 9 + tap];
        uint32_t logical = (uint32_t)(combo * 1024 + lane2 * 32 + slot * 4);
        *(uint32_t*)((char*)swf + bswz(logical)) = bf16_hi_lo_pack(v0, v1, hl);
    }
    if (tid < 32) sbias[tid] = bias[g * 32 + tid];
    __syncthreads();

    // ---- main: warp = (row, w-half); 2 halves of 2 segs each ----
    const int wrow  = wid >> 1;          // 0..3
    const int whalf = (wid & 1) * 64;
    const int g4 = lane >> 2, t4 = lane & 3;
    const int h = h0 + wrow;
    float* og = out + (size_t)(n * 512 + g * 32) * 16384 + (size_t)h * 128;

    // per-thread invariant part of the A address
    const uint32_t baseA = (uint32_t)(wrow * XROW_STRIDE + g4 * XCOL_STRIDE + t4 * 4);
    const uint32_t bswF = bswz((uint32_t)(lane * 32));   // lane's swizzled frag offset

    #pragma unroll
    for (int half = 0; half < 2; ++half) {
        float acc[2][4][4];              // [seg2][nt][4]
        #pragma unroll
        for (int s = 0; s < 2; ++s)
            #pragma unroll
            for (int nt = 0; nt < 4; ++nt)
                #pragma unroll
                for (int i = 0; i < 4; ++i) acc[s][nt][i] = 0.0f;

        #pragma unroll 3
        for (int tap = 0; tap < 9; ++tap) {
            const int dh = tap / 3, dw = tap % 3;
            // B fragments (hi @ combo 2*tap, lo @ +1024B); swizzle preserved by +2048*tap
            const char* bp = (const char*)swf + (uint32_t)(tap * 2048) + bswF;
            uint4 bh0 = *(const uint4*)(bp);
            uint4 bh1 = *(const uint4*)((const char*)swf + (((uint32_t)(tap * 2048) + bswF) ^ 16));
            uint4 bl0 = *(const uint4*)(bp + 1024);
            uint4 bl1 = *(const uint4*)((const char*)swf + ((((uint32_t)(tap * 2048) + bswF) ^ 16) + 1024));

            #pragma unroll
            for (int s = 0; s < 2; ++s) {
                const int w0 = whalf + (half * 2 + s) * 16;
                const uint32_t off = baseA + (uint32_t)(dh * XROW_STRIDE + (w0 + dw) * XCOL_STRIDE);

                uint32_t ah0 = *(const uint32_t*)(sxh + off);
                uint32_t ah1 = *(const uint32_t*)(sxh + off + 8 * XCOL_STRIDE);
                uint32_t ah2 = *(const uint32_t*)(sxh + off + 16);
                uint32_t ah3 = *(const uint32_t*)(sxh + off + 8 * XCOL_STRIDE + 16);
                uint32_t al0 = *(const uint32_t*)(sxl + off);
                uint32_t al1 = *(const uint32_t*)(sxl + off + 8 * XCOL_STRIDE);
                uint32_t al2 = *(const uint32_t*)(sxl + off + 16);
                uint32_t al3 = *(const uint32_t*)(sxl + off + 8 * XCOL_STRIDE + 16);

                float* a0 = acc[s][0];
                float* a1 = acc[s][1];
                float* a2 = acc[s][2];
                float* a3 = acc[s][3];

                mma16816(a0[0], a0[1], a0[2], a0[3], ah0, ah1, ah2, ah3, bh0.x, bh0.y);
                mma16816(a1[0], a1[1], a1[2], a1[3], ah0, ah1, ah2, ah3, bh0.z, bh0.w);
                mma16816(a2[0], a2[1], a2[2], a2[3], ah0, ah1, ah2, ah3, bh1.x, bh1.y);
                mma16816(a3[0], a3[1], a3[2], a3[3], ah0, ah1, ah2, ah3, bh1.z, bh1.w);

                mma16816(a0[0], a0[1], a0[2], a0[3], ah0, ah1, ah2, ah3, bl0.x, bl0.y);
                mma16816(a1[0], a1[1], a1[2], a1[3], ah0, ah1, ah2, ah3, bl0.z, bl0.w);
                mma16816(a2[0], a2[1], a2[2], a2[3], ah0, ah1, ah2, ah3, bl1.x, bl1.y);
                mma16816(a3[0], a3[1], a3[2], a3[3], ah0, ah1, ah2, ah3, bl1.z, bl1.w);

                mma16816(a0[0], a0[1], a0[2], a0[3], al0, al1, al2, al3, bh0.x, bh0.y);
                mma16816(a1[0], a1[1], a1[2], a1[3], al0, al1, al2, al3, bh0.z, bh0.w);
                mma16816(a2[0], a2[1], a2[2], a2[3], al0, al1, al2, al3, bh1.x, bh1.y);
                mma16816(a3[0], a3[1], a3[2], a3[3], al0, al1, al2, al3, bh1.z, bh1.w);
            }
        }

        // ---- epilogue for this half (bias loaded late to cut live ranges) ----
        #pragma unroll
        for (int s = 0; s < 2; ++s) {
            const int w0 = whalf + (half * 2 + s) * 16;
            #pragma unroll
            for (int nt = 0; nt < 4; ++nt) {
                const float blo = sbias[nt * 8 + 2 * t4];
                const float bhi = sbias[nt * 8 + 2 * t4 + 1];
                const size_t co0 = (size_t)(nt * 8 + 2 * t4) * 16384;
                og[co0 + w0 + g4]             = acc[s][nt][0] + blo;
                og[co0 + 16384 + w0 + g4]     = acc[s][nt][1] + bhi;
                og[co0 + w0 + g4 + 8]         = acc[s][nt][2] + blo;
                og[co0 + 16384 + w0 + g4 + 8] = acc[s][nt][3] + bhi;
            }
        }
    }
}

extern "C" void kernel_launch(void* const* d_in, const int* in_sizes, int n_in,
                              void* d_out, int out_size)
{
    const float* x = (const float*)d_in[0];
    const float* w = (const float*)d_in[1];
    const float* b = (const float*)d_in[2];
    float* out = (float*)d_out;

    cudaFuncSetAttribute(grouped_conv_hmma,
                         cudaFuncAttributeMaxDynamicSharedMemorySize, SMEM_TOTAL);

    dim3 grid(32, 256);   // 4-row h blocks, n*16+g
    grouped_conv_hmma<<<grid, THREADS, SMEM_TOTAL>>>(x, w, b, out);
}

// round 8
// speedup vs baseline: 2.0315x; 1.0049x over previous
#include <cuda_runtime.h>
#include <cuda_bf16.h>
#include <cstdint>

// Grouped conv2d via implicit GEMM on mma.sync (HMMA), split-bf16 3-pass.
// x[16,256,128,128] * W[512,16,3,3] (groups=16) + b -> out[16,512,128,128]
// R8: conflict-free dense x planes (32B/px, XOR swizzle) + ci permutation so
//     each A fragment half is one LDS.64. 3 CTAs/SM, acc=32 regs (half-split).

#define THREADS 256

// ---- smem layout (bytes) ----
// B frags: 18 combos x 1024B (32 lanes x 32B), 16B-block XOR swizzle
#define SWF_OFF   0
#define SWF_BYTES (18 * 1024)               // 18432
// x planes hi/lo: [row 0..5][col 0..129] x 32B (16 ci bf16, permuted), dense
#define XCOL_STRIDE 32
#define XROW_STRIDE (130 * XCOL_STRIDE)     // 4160
#define XPLANE_BYTES (6 * XROW_STRIDE)      // 24960
#define SXH_OFF   SWF_BYTES                 // 18432
#define SXL_OFF   (SXH_OFF + XPLANE_BYTES)  // 43392
#define SBIAS_OFF (SXL_OFF + XPLANE_BYTES)  // 68352
#define SMEM_TOTAL (SBIAS_OFF + 128)        // 68480  (x3 = 205440 <= 228KB)

__device__ __forceinline__ void mma16816(float& c0, float& c1, float& c2, float& c3,
                                         uint32_t a0, uint32_t a1, uint32_t a2, uint32_t a3,
                                         uint32_t b0, uint32_t b1) {
    asm volatile("mma.sync.aligned.m16n8k16.row.col.f32.bf16.bf16.f32 "
                 "{%0,%1,%2,%3}, {%4,%5,%6,%7}, {%8,%9}, {%0,%1,%2,%3};"
                 : "+f"(c0), "+f"(c1), "+f"(c2), "+f"(c3)
                 : "r"(a0), "r"(a1), "r"(a2), "r"(a3), "r"(b0), "r"(b1));
}

__device__ __forceinline__ uint32_t bf16_hi_lo_pack(float v0, float v1, int want_lo) {
    __nv_bfloat16 h0 = __float2bfloat16(v0);
    __nv_bfloat16 h1 = __float2bfloat16(v1);
    __nv_bfloat16 e0, e1;
    if (want_lo) {
        e0 = __float2bfloat16(v0 - __bfloat162float(h0));
        e1 = __float2bfloat16(v1 - __bfloat162float(h1));
    } else {
        e0 = h0; e1 = h1;
    }
    return (uint32_t)__bfloat16_as_ushort(e0) | ((uint32_t)__bfloat16_as_ushort(e1) << 16);
}

// 1-bit XOR swizzle: fold px bit2 (byte-addr bit 7) into bank bit 4
__device__ __forceinline__ uint32_t xswz(uint32_t off) {
    return off ^ (((off >> 7) & 1u) << 4);
}
__device__ __forceinline__ uint32_t bswz(uint32_t logical) {
    return logical ^ (((logical >> 7) & 1u) << 4);
}

__global__ __launch_bounds__(THREADS, 3)
void grouped_conv_hmma(const float* __restrict__ x,
                       const float* __restrict__ w,
                       const float* __restrict__ bias,
                       float* __restrict__ out)
{
    extern __shared__ char smem[];
    uint32_t* swf = (uint32_t*)(smem + SWF_OFF);
    char* sxh = smem + SXH_OFF;
    char* sxl = smem + SXL_OFF;
    float* sbias = (float*)(smem + SBIAS_OFF);

    const int tid = threadIdx.x;
    const int wid = tid >> 5;
    const int lane = tid & 31;

    const int hb = blockIdx.x;          // 0..31  (4-row blocks)
    const int ng = blockIdx.y;          // 0..255
    const int n  = ng >> 4;
    const int g  = ng & 15;
    const int h0 = hb * 4;

    // ---- stage x: rows h0-1..h0+4, cols -1..128 ----
    // ci pair j stored at physical pair (j&3)*2 + (j>>2)  (=> per-thread LDS.64 frags)
    const float* xg = x + (size_t)(n * 256 + g * 16) * 16384;
    for (int idx = tid; idx < 6 * 8 * 130; idx += THREADS) {
        int c   = idx % 130;
        int t   = idx / 130;
        int j   = t % 8;                // logical ci pair
        int r   = t / 8;                // 0..5
        int gh = h0 - 1 + r;
        int gw = c - 1;
        float v0 = 0.0f, v1 = 0.0f;
        if ((unsigned)gh < 128u && (unsigned)gw < 128u) {
            const float* p = xg + (j * 2) * 16384 + gh * 128 + gw;
            v0 = p[0];
            v1 = p[16384];
        }
        int phys = (j & 3) * 2 + (j >> 2);
        uint32_t off = (uint32_t)(r * XROW_STRIDE + c * XCOL_STRIDE + phys * 4);
        uint32_t so = xswz(off);
        *(uint32_t*)(sxh + so) = bf16_hi_lo_pack(v0, v1, 0);
        *(uint32_t*)(sxl + so) = bf16_hi_lo_pack(v0, v1, 1);
    }

    // ---- stage W as B fragments, XOR-swizzled 32B/lane ----
    const float* wgp = w + (size_t)(g * 32) * 144;
    for (int idx = tid; idx < 18 * 32 * 8; idx += THREADS) {
        int slot  = idx & 7;
        int lane2 = (idx >> 3) & 31;
        int combo = idx >> 8;           // 0..17 = tap*2 + hl
        int tap = combo >> 1, hl = combo & 1;
        int g4 = lane2 >> 2, t4 = lane2 & 3;
        int nt = slot >> 1, rr = slot & 1;
        int co  = nt * 8 + g4;
        int ci0 = 2 * t4 + 8 * rr;
        float v0 = wgp[co * 144 + ci0 * 9 + tap];
        float v1 = wgp[co * 144 + (ci0 + 1) * 9 + tap];
        uint32_t logical = (uint32_t)(combo * 1024 + lane2 * 32 + slot * 4);
        *(uint32_t*)((char*)swf + bswz(logical)) = bf16_hi_lo_pack(v0, v1, hl);
    }
    if (tid < 32) sbias[tid] = bias[g * 32 + tid];
    __syncthreads();

    // ---- main: warp = (row, w-half); 2 halves of 2 segs each ----
    const int wrow  = wid >> 1;          // 0..3
    const int whalf = (wid & 1) * 64;
    const int g4 = lane >> 2, t4 = lane & 3;
    const int h = h0 + wrow;
    float* og = out + (size_t)(n * 512 + g * 32) * 16384 + (size_t)h * 128;

    // per-thread invariant part of the A offset (within a row): pixel g4, frag t4
    const uint32_t pxoff = (uint32_t)(g4 * XCOL_STRIDE + t4 * 8);
    const uint32_t bswF = bswz((uint32_t)(lane * 32));   // lane's swizzled B-frag offset

    #pragma unroll
    for (int half = 0; half < 2; ++half) {
        float acc[2][4][4];              // [seg2][nt][4]
        #pragma unroll
        for (int s = 0; s < 2; ++s)
            #pragma unroll
            for (int nt = 0; nt < 4; ++nt)
                #pragma unroll
                for (int i = 0; i < 4; ++i) acc[s][nt][i] = 0.0f;

        #pragma unroll 3
        for (int tap = 0; tap < 9; ++tap) {
            const int dh = tap / 3, dw = tap % 3;
            // B fragments (hi @ combo 2*tap, lo @ +1024B)
            const uint32_t bo = (uint32_t)(tap * 2048) + bswF;
            uint4 bh0 = *(const uint4*)((const char*)swf + bo);
            uint4 bh1 = *(const uint4*)((const char*)swf + (bo ^ 16));
            uint4 bl0 = *(const uint4*)((const char*)swf + bo + 1024);
            uint4 bl1 = *(const uint4*)((const char*)swf + (bo ^ 16) + 1024);

            #pragma unroll
            for (int s = 0; s < 2; ++s) {
                const int w0 = whalf + (half * 2 + s) * 16;
                uint32_t off = (uint32_t)((wrow + dh) * XROW_STRIDE
                                        + (w0 + dw) * XCOL_STRIDE) + pxoff;
                uint32_t so = xswz(off);          // +256 (px+8) preserves swizzle

                uint2 h01 = *(const uint2*)(sxh + so);         // a0 (v.x), a2 (v.y)
                uint2 h23 = *(const uint2*)(sxh + so + 256);   // a1, a3 (px g4+8)
                uint2 l01 = *(const uint2*)(sxl + so);
                uint2 l23 = *(const uint2*)(sxl + so + 256);

                float* a0 = acc[s][0];
                float* a1 = acc[s][1];
                float* a2 = acc[s][2];
                float* a3 = acc[s][3];

                mma16816(a0[0], a0[1], a0[2], a0[3], h01.x, h23.x, h01.y, h23.y, bh0.x, bh0.y);
                mma16816(a1[0], a1[1], a1[2], a1[3], h01.x, h23.x, h01.y, h23.y, bh0.z, bh0.w);
                mma16816(a2[0], a2[1], a2[2], a2[3], h01.x, h23.x, h01.y, h23.y, bh1.x, bh1.y);
                mma16816(a3[0], a3[1], a3[2], a3[3], h01.x, h23.x, h01.y, h23.y, bh1.z, bh1.w);

                mma16816(a0[0], a0[1], a0[2], a0[3], h01.x, h23.x, h01.y, h23.y, bl0.x, bl0.y);
                mma16816(a1[0], a1[1], a1[2], a1[3], h01.x, h23.x, h01.y, h23.y, bl0.z, bl0.w);
                mma16816(a2[0], a2[1], a2[2], a2[3], h01.x, h23.x, h01.y, h23.y, bl1.x, bl1.y);
                mma16816(a3[0], a3[1], a3[2], a3[3], h01.x, h23.x, h01.y, h23.y, bl1.z, bl1.w);

                mma16816(a0[0], a0[1], a0[2], a0[3], l01.x, l23.x, l01.y, l23.y, bh0.x, bh0.y);
                mma16816(a1[0], a1[1], a1[2], a1[3], l01.x, l23.x, l01.y, l23.y, bh0.z, bh0.w);
                mma16816(a2[0], a2[1], a2[2], a2[3], l01.x, l23.x, l01.y, l23.y, bh1.x, bh1.y);
                mma16816(a3[0], a3[1], a3[2], a3[3], l01.x, l23.x, l01.y, l23.y, bh1.z, bh1.w);
            }
        }

        // ---- epilogue for this half ----
        #pragma unroll
        for (int s = 0; s < 2; ++s) {
            const int w0 = whalf + (half * 2 + s) * 16;
            #pragma unroll
            for (int nt = 0; nt < 4; ++nt) {
                const float blo = sbias[nt * 8 + 2 * t4];
                const float bhi = sbias[nt * 8 + 2 * t4 + 1];
                const size_t co0 = (size_t)(nt * 8 + 2 * t4) * 16384;
                og[co0 + w0 + g4]             = acc[s][nt][0] + blo;
                og[co0 + 16384 + w0 + g4]     = acc[s][nt][1] + bhi;
                og[co0 + w0 + g4 + 8]         = acc[s][nt][2] + blo;
                og[co0 + 16384 + w0 + g4 + 8] = acc[s][nt][3] + bhi;
            }
        }
    }
}

extern "C" void kernel_launch(void* const* d_in, const int* in_sizes, int n_in,
                              void* d_out, int out_size)
{
    const float* x = (const float*)d_in[0];
    const float* w = (const float*)d_in[1];
    const float* b = (const float*)d_in[2];
    float* out = (float*)d_out;

    cudaFuncSetAttribute(grouped_conv_hmma,
                         cudaFuncAttributeMaxDynamicSharedMemorySize, SMEM_TOTAL);

    dim3 grid(32, 256);   // 4-row h blocks, n*16+g
    grouped_conv_hmma<<<grid, THREADS, SMEM_TOTAL>>>(x, w, b, out);
}